// round 17
// baseline (speedup 1.0000x reference)
#include <cuda_runtime.h>

// LineGraphic2d: 8192x8192 fp32 canvas, 6px-wide capsule nonzero (0.06%).
// R17 probe: split into (1) cudaMemsetAsync zero-fill of the full canvas
// (pure driver fill path - tests whether it beats the ~6.8 TB/s compute-store
// stream) and (2) a sparse band kernel writing ONLY the ~45k nonzero pixels.
// Band kernel: one block/row; conservative x-interval from dist-to-infinite-
// line <= 3.5 intersected with the segment x-cap (+/-4.5) - a proven superset
// of the capsule (dist-to-line <= dist-to-segment). Inside the interval, the
// bit-exact XLA chain (unfused fp32 + div.full.f32, mask e2 < 9) decides and
// writes values; zeros are never written (memset owns them).

#define H 8192
#define W 8192
#define EPSILON_F 0.001f

__device__ __forceinline__ float div_full(float a, float b) {
    float r;
    asm("div.full.f32 %0, %1, %2;" : "=f"(r) : "f"(a), "f"(b));
    return r;
}

__global__ void __launch_bounds__(64) band_kernel(
    const float* __restrict__ kp, float* __restrict__ out)
{
    const int y = blockIdx.x;

    // key_points [2,2]: rows=(p0,p1), cols=(y,x). x8192 = power-of-two: exact,
    // so p0, d match the reference's fp32 scalars bit-for-bit.
    const float4 k = *reinterpret_cast<const float4*>(kp);
    const float p0y = __fmul_rn(k.x, (float)H);
    const float p0x = __fmul_rn(k.y, (float)W);
    const float dy  = __fsub_rn(__fmul_rn(k.z, (float)H), p0y);
    const float dx  = __fsub_rn(__fmul_rn(k.w, (float)W), p0x);
    const float len2 = __fadd_rn(__fmul_rn(dy, dy), __fmul_rn(dx, dx));   // ref rounding
    const float len  = __fsqrt_rn(len2);
    const float inv_maxd = __frcp_rn(__fsqrt_rn(134217728.0f));           // 1/norm([8192,8192])

    const float ry = __fsub_rn((float)y, p0y);
    const float ry_dy = __fmul_rn(ry, dy);              // ref's per-row product

    // Conservative x-interval for this row:
    // dist-to-infinite-line <= 3.5  <=>  |(x-p0x)*dy - ry*dx| <= 3.5*len
    const float c = ry * dx;
    const float m = 3.5f * len;
    float xlo_f, xhi_f;
    if (fabsf(dy) > 1e-3f) {
        const float a = (c - m) / dy + p0x;
        const float b = (c + m) / dy + p0x;
        xlo_f = fminf(a, b);
        xhi_f = fmaxf(a, b);
    } else {
        // near-horizontal-in-y line: row in band iff |c| <= m (uniform per block)
        if (fabsf(c) > m) return;
        xlo_f = 0.0f;
        xhi_f = (float)(W - 1);
    }
    // Segment x-cap (endpoint caps), generous padding for all fp slop
    const float capxlo = fminf(p0x, p0x + dx) - 4.5f;
    const float capxhi = fmaxf(p0x, p0x + dx) + 4.5f;
    const int lo = max(0,     (int)floorf(fmaxf(xlo_f - 2.0f, capxlo)));
    const int hi = min(W - 1, (int)ceilf (fminf(xhi_f + 2.0f, capxhi)));
    if (lo > hi) return;

    for (int x = lo + (int)threadIdx.x; x <= hi; x += 64) {
        // bit-exact ref chain: unfused fp32 + div.full.f32
        const float rx = __fsub_rn((float)x, p0x);
        float t = div_full(__fadd_rn(ry_dy, __fmul_rn(rx, dx)), len2);
        t = fminf(fmaxf(t, 0.0f), 1.0f);
        const float ey = __fsub_rn(ry, __fmul_rn(t, dy));
        const float ex = __fsub_rn(rx, __fmul_rn(t, dx));
        const float e2 = fmaxf(__fadd_rn(__fmul_rn(ey, ey), __fmul_rn(ex, ex)), 1e-12f);
        if (e2 < 9.0f) {   // dist<3 <=> e2<9 (sqrt.rn monotone, 9 exact)
            const float dist = __fsqrt_rn(e2);
            out[(size_t)y * W + x] = 1.0f - __fmaf_rn(dist, inv_maxd, EPSILON_F);
        }
    }
}

extern "C" void kernel_launch(void* const* d_in, const int* in_sizes, int n_in,
                              void* d_out, int out_size)
{
    const float* kp = (const float*)d_in[0];
    float* out = (float*)d_out;
    // (1) zero-fill background via driver fill path (graph-capturable)
    cudaMemsetAsync(d_out, 0, (size_t)H * W * sizeof(float), 0);
    // (2) write only the nonzero band pixels (same stream -> ordered)
    band_kernel<<<H, 64>>>(kp, out);
}